// round 15
// baseline (speedup 1.0000x reference)
#include <cuda_runtime.h>
#include <cuda_fp16.h>
#include <math.h>
#include <stdint.h>

#define BB 32
#define TF 2048
#define TP 256
#define FD 768
#define PD 512
#define AD 512
typedef __half h16;

// ---------------- device scratch ----------------
__device__ h16 g_fh[(size_t)BB * TF * FD];                       // frame fp16
__device__ h16 g_ph[(size_t)BB * TP * PD], g_pl[(size_t)BB * TP * PD];
__device__ h16 g_wqh[AD * FD];                                   // Wq^T fp16
__device__ h16 g_wkh[AD * PD], g_wkl[AD * PD];
__device__ h16 g_qh[(size_t)BB * TF * AD], g_ql[(size_t)BB * TF * AD];
__device__ h16 g_kh[(size_t)BB * TP * AD], g_kl[(size_t)BB * TP * AD];
__device__ h16 g_kth[(size_t)BB * AD * TP], g_ktl[(size_t)BB * AD * TP];
__device__ h16 g_Ph[(size_t)BB * TF * TP];
__device__ h16 g_att[(size_t)BB * TF * AD];   // fp16 scratch (pre-LN att)

// ---------------- helpers ----------------
__device__ __forceinline__ uint32_t s2u(const void* p) {
    uint32_t a;
    asm("{ .reg .u64 t; cvta.to.shared.u64 t, %1; cvt.u32.u64 %0, t; }"
        : "=r"(a) : "l"(p));
    return a;
}
__device__ __forceinline__ void split1h(float v, h16& h, h16& l) {
    h = __float2half_rn(v);
    l = __float2half_rn(v - __half2float(h));
}
__device__ __forceinline__ uint32_t pack2h(h16 a, h16 b) {
    __half2 v; v.x = a; v.y = b;
    return *(uint32_t*)&v;
}
__device__ __forceinline__ void cp16(uint32_t dst, const void* src) {
    asm volatile("cp.async.cg.shared.global [%0], [%1], 16;" :: "r"(dst), "l"(src));
}
__device__ __forceinline__ void cp_commit() { asm volatile("cp.async.commit_group;"); }
template <int N>
__device__ __forceinline__ void cp_wait() {
    asm volatile("cp.async.wait_group %0;" :: "n"(N));
}
__device__ __forceinline__ void ldm4(uint32_t* r, uint32_t addr) {
    asm volatile("ldmatrix.sync.aligned.m8n8.x4.shared.b16 {%0,%1,%2,%3}, [%4];"
                 : "=r"(r[0]), "=r"(r[1]), "=r"(r[2]), "=r"(r[3]) : "r"(addr));
}
__device__ __forceinline__ void mma_h(float* c, const uint32_t* a,
                                      uint32_t b0, uint32_t b1) {
    asm volatile("mma.sync.aligned.m16n8k16.row.col.f32.f16.f16.f32 "
                 "{%0,%1,%2,%3}, {%4,%5,%6,%7}, {%8,%9}, {%0,%1,%2,%3};"
                 : "+f"(c[0]), "+f"(c[1]), "+f"(c[2]), "+f"(c[3])
                 : "r"(a[0]), "r"(a[1]), "r"(a[2]), "r"(a[3]), "r"(b0), "r"(b1));
}
__device__ __forceinline__ float fexp(float x) {
    float y = fmaxf(x * 1.44269504f, -125.0f);
    float i = rintf(y);
    float f = y - i;
    float p = 1.3333558146e-3f;
    p = fmaf(p, f, 9.6181291076e-3f);
    p = fmaf(p, f, 5.5504108664e-2f);
    p = fmaf(p, f, 2.4022650696e-1f);
    p = fmaf(p, f, 6.9314718056e-1f);
    p = fmaf(p, f, 1.0f);
    float s = __int_as_float(((int)i + 127) << 23);
    return p * s;
}
// 64B-row swizzle: row*64 bytes, 16B unit q in 0..3, XOR with (row>>1)&3
__device__ __forceinline__ uint32_t soff(int row, int q) {
    return (uint32_t)(row * 64 + ((q ^ ((row >> 1) & 3)) << 4));
}
// cp.async [ROWS x 32] fp16 K-major tile into swizzled smem (256 threads)
template <int ROWS>
__device__ __forceinline__ void ldth(const h16* __restrict__ src, size_t row0,
                                     int ld, int k0, uint32_t dst, int t) {
#pragma unroll
    for (int it = 0; it < ROWS / 64; it++) {
        int u = it * 256 + t;
        int row = u >> 2, q = u & 3;
        cp16(dst + soff(row, q), src + (row0 + row) * (size_t)ld + k0 + q * 8);
    }
}

// ===== gemm1: 1-pass fp16 C[128,128] = A[128,K] @ B[128,K]^T (projQ) ======
#define G1_SMEM 32768
__global__ __launch_bounds__(256, 2)
void gemm1(const h16* __restrict__ Ah, int lda, const h16* __restrict__ Bh,
           int ldb, int K, const float* __restrict__ bias) {
    extern __shared__ char sm[];
    const uint32_t sbase = s2u(sm);
    const int t = threadIdx.x, lane = t & 31, wid = t >> 5;
    const int wm = wid >> 1, wn = wid & 1;
    const size_t arow0 = (size_t)blockIdx.y * 128;
    const size_t brow0 = (size_t)blockIdx.x * 128;
    const int NC = K / 32;

    float acc[2][8][4];
#pragma unroll
    for (int mt = 0; mt < 2; mt++)
#pragma unroll
        for (int nt = 0; nt < 8; nt++)
#pragma unroll
            for (int j = 0; j < 4; j++) acc[mt][nt][j] = 0.0f;

    ldth<128>(Ah, arow0, lda, 0, sbase, t);
    ldth<128>(Bh, brow0, ldb, 0, sbase + 8192, t);
    cp_commit();

    for (int c = 0; c < NC; c++) {
        if (c + 1 < NC) {
            uint32_t sn = sbase + ((c + 1) & 1) * 16384;
            ldth<128>(Ah, arow0, lda, (c + 1) * 32, sn, t);
            ldth<128>(Bh, brow0, ldb, (c + 1) * 32, sn + 8192, t);
            cp_commit();
            cp_wait<1>();
        } else {
            cp_wait<0>();
        }
        __syncthreads();
        const uint32_t s = sbase + (c & 1) * 16384;
#pragma unroll
        for (int ks = 0; ks < 2; ks++) {
            uint32_t a[2][4], bb[8][2];
#pragma unroll
            for (int mt = 0; mt < 2; mt++) {
                int row = wm * 32 + mt * 16 + (lane & 15);
                int q = ks * 2 + (lane >> 4);
                ldm4(a[mt], s + soff(row, q));
            }
            const int g = lane >> 3, w = lane & 7;
#pragma unroll
            for (int np = 0; np < 4; np++) {
                int ntl = np * 2 + (g >> 1);
                int row = wn * 64 + ntl * 8 + w;
                int q = ks * 2 + (g & 1);
                uint32_t r4[4];
                ldm4(r4, s + 8192 + soff(row, q));
                bb[np * 2][0] = r4[0]; bb[np * 2][1] = r4[1];
                bb[np * 2 + 1][0] = r4[2]; bb[np * 2 + 1][1] = r4[3];
            }
#pragma unroll
            for (int mt = 0; mt < 2; mt++)
#pragma unroll
                for (int nt = 0; nt < 8; nt++)
                    mma_h(acc[mt][nt], a[mt], bb[nt][0], bb[nt][1]);
        }
        __syncthreads();
    }
#pragma unroll
    for (int mt = 0; mt < 2; mt++)
#pragma unroll
        for (int h = 0; h < 2; h++) {
            const int rl = wm * 32 + mt * 16 + (lane >> 2) + h * 8;
            const size_t gr = (size_t)blockIdx.y * 128 + rl;
#pragma unroll
            for (int nt = 0; nt < 8; nt++) {
                const int cl = wn * 64 + nt * 8 + (lane & 3) * 2;
                const int gc = blockIdx.x * 128 + cl;
                float v0 = acc[mt][nt][h * 2] + bias[gc];
                float v1 = acc[mt][nt][h * 2 + 1] + bias[gc + 1];
                h16 h0, l0, h1, l1;
                split1h(v0, h0, l0);
                split1h(v1, h1, l1);
                *(uint32_t*)&g_qh[gr * AD + gc] = pack2h(h0, h1);
                *(uint32_t*)&g_ql[gr * AD + gc] = pack2h(l0, l1);
            }
        }
}

// ===== gemm3: 3-pass fp16 split (projK) ===================================
#define G3_SMEM 65536
__global__ __launch_bounds__(256, 2)
void gemm3(const h16* __restrict__ Ah, const h16* __restrict__ Al, int lda,
           const h16* __restrict__ Bh, const h16* __restrict__ Bl,
           int ldb, int K, const float* __restrict__ bias) {
    extern __shared__ char sm[];
    const uint32_t sbase = s2u(sm);
    const int t = threadIdx.x, lane = t & 31, wid = t >> 5;
    const int wm = wid >> 1, wn = wid & 1;
    const size_t arow0 = (size_t)blockIdx.y * 128;
    const size_t brow0 = (size_t)blockIdx.x * 128;
    const int NC = K / 32;

    float acc[2][8][4];
#pragma unroll
    for (int mt = 0; mt < 2; mt++)
#pragma unroll
        for (int nt = 0; nt < 8; nt++)
#pragma unroll
            for (int j = 0; j < 4; j++) acc[mt][nt][j] = 0.0f;

    ldth<128>(Ah, arow0, lda, 0, sbase, t);
    ldth<128>(Al, arow0, lda, 0, sbase + 8192, t);
    ldth<128>(Bh, brow0, ldb, 0, sbase + 16384, t);
    ldth<128>(Bl, brow0, ldb, 0, sbase + 24576, t);
    cp_commit();

    for (int c = 0; c < NC; c++) {
        if (c + 1 < NC) {
            uint32_t sn = sbase + ((c + 1) & 1) * 32768;
            const int k0 = (c + 1) * 32;
            ldth<128>(Ah, arow0, lda, k0, sn, t);
            ldth<128>(Al, arow0, lda, k0, sn + 8192, t);
            ldth<128>(Bh, brow0, ldb, k0, sn + 16384, t);
            ldth<128>(Bl, brow0, ldb, k0, sn + 24576, t);
            cp_commit();
            cp_wait<1>();
        } else {
            cp_wait<0>();
        }
        __syncthreads();
        const uint32_t s = sbase + (c & 1) * 32768;
#pragma unroll
        for (int ks = 0; ks < 2; ks++) {
            uint32_t ah[2][4], al[2][4], bh[8][2], bl[8][2];
#pragma unroll
            for (int mt = 0; mt < 2; mt++) {
                int row = wm * 32 + mt * 16 + (lane & 15);
                int q = ks * 2 + (lane >> 4);
                uint32_t off = soff(row, q);
                ldm4(ah[mt], s + off);
                ldm4(al[mt], s + 8192 + off);
            }
            const int g = lane >> 3, w = lane & 7;
#pragma unroll
            for (int np = 0; np < 4; np++) {
                int ntl = np * 2 + (g >> 1);
                int row = wn * 64 + ntl * 8 + w;
                int q = ks * 2 + (g & 1);
                uint32_t off = soff(row, q);
                uint32_t r4[4];
                ldm4(r4, s + 16384 + off);
                bh[np * 2][0] = r4[0]; bh[np * 2][1] = r4[1];
                bh[np * 2 + 1][0] = r4[2]; bh[np * 2 + 1][1] = r4[3];
                ldm4(r4, s + 24576 + off);
                bl[np * 2][0] = r4[0]; bl[np * 2][1] = r4[1];
                bl[np * 2 + 1][0] = r4[2]; bl[np * 2 + 1][1] = r4[3];
            }
#pragma unroll
            for (int mt = 0; mt < 2; mt++)
#pragma unroll
                for (int nt = 0; nt < 8; nt++) {
                    mma_h(acc[mt][nt], ah[mt], bh[nt][0], bh[nt][1]);
                    mma_h(acc[mt][nt], ah[mt], bl[nt][0], bl[nt][1]);
                    mma_h(acc[mt][nt], al[mt], bh[nt][0], bh[nt][1]);
                }
        }
        __syncthreads();
    }

#pragma unroll
    for (int mt = 0; mt < 2; mt++)
#pragma unroll
        for (int h = 0; h < 2; h++) {
            const int rl = wm * 32 + mt * 16 + (lane >> 2) + h * 8;
            const size_t gr = (size_t)blockIdx.y * 128 + rl;
#pragma unroll
            for (int nt = 0; nt < 8; nt++) {
                const int cl = wn * 64 + nt * 8 + (lane & 3) * 2;
                const int gc = blockIdx.x * 128 + cl;
                float v0 = acc[mt][nt][h * 2] + bias[gc];
                float v1 = acc[mt][nt][h * 2 + 1] + bias[gc + 1];
                h16 h0, l0, h1, l1;
                split1h(v0, h0, l0);
                split1h(v1, h1, l1);
                *(uint32_t*)&g_kh[gr * AD + gc] = pack2h(h0, h1);
                *(uint32_t*)&g_kl[gr * AD + gc] = pack2h(l0, l1);
                const int bb = (int)(gr >> 8), p = (int)(gr & 255);
                g_kth[((size_t)bb * AD + gc) * TP + p] = h0;
                g_ktl[((size_t)bb * AD + gc) * TP + p] = l0;
                g_kth[((size_t)bb * AD + gc + 1) * TP + p] = h1;
                g_ktl[((size_t)bb * AD + gc + 1) * TP + p] = l1;
            }
        }
}

// ===== energy_sm: 2-pass energy (64x256 tile) + mask + fused softmax ======
// stage: A 4K | Bh 16K | Bl 16K = 36K; double-buffered 72K; E reuses buffers.
#define GE_SMEM 73728
__global__ __launch_bounds__(256, 2)
void energy_sm(const h16* __restrict__ Ah,
               const h16* __restrict__ Bh, const h16* __restrict__ Bl,
               const int* __restrict__ amask, float* __restrict__ energy_out) {
    extern __shared__ char sm[];
    const uint32_t sbase = s2u(sm);
    const int t = threadIdx.x, lane = t & 31, wid = t >> 5;
    const int wm = wid >> 2, wn = wid & 3;  // 2 x 4 warps, warp tile 32 x 64
    const int b = blockIdx.z;
    const size_t arow0 = (size_t)b * TF + (size_t)blockIdx.y * 64;
    const size_t brow0 = (size_t)b * TP;
    const int NC = AD / 32;

    float acc[2][8][4];
#pragma unroll
    for (int mt = 0; mt < 2; mt++)
#pragma unroll
        for (int nt = 0; nt < 8; nt++)
#pragma unroll
            for (int j = 0; j < 4; j++) acc[mt][nt][j] = 0.0f;

    ldth<64>(Ah, arow0, AD, 0, sbase, t);
    ldth<256>(Bh, brow0, AD, 0, sbase + 4096, t);
    ldth<256>(Bl, brow0, AD, 0, sbase + 20480, t);
    cp_commit();

    for (int c = 0; c < NC; c++) {
        if (c + 1 < NC) {
            uint32_t sn = sbase + ((c + 1) & 1) * 36864;
            const int k0 = (c + 1) * 32;
            ldth<64>(Ah, arow0, AD, k0, sn, t);
            ldth<256>(Bh, brow0, AD, k0, sn + 4096, t);
            ldth<256>(Bl, brow0, AD, k0, sn + 20480, t);
            cp_commit();
            cp_wait<1>();
        } else {
            cp_wait<0>();
        }
        __syncthreads();
        const uint32_t s = sbase + (c & 1) * 36864;
#pragma unroll
        for (int ks = 0; ks < 2; ks++) {
            uint32_t a[2][4], bh[8][2], bl[8][2];
#pragma unroll
            for (int mt = 0; mt < 2; mt++) {
                int row = wm * 32 + mt * 16 + (lane & 15);
                int q = ks * 2 + (lane >> 4);
                ldm4(a[mt], s + soff(row, q));
            }
            const int g = lane >> 3, w = lane & 7;
#pragma unroll
            for (int np = 0; np < 4; np++) {
                int ntl = np * 2 + (g >> 1);
                int row = wn * 64 + ntl * 8 + w;
                int q = ks * 2 + (g & 1);
                uint32_t off = soff(row, q);
                uint32_t r4[4];
                ldm4(r4, s + 4096 + off);
                bh[np * 2][0] = r4[0]; bh[np * 2][1] = r4[1];
                bh[np * 2 + 1][0] = r4[2]; bh[np * 2 + 1][1] = r4[3];
                ldm4(r4, s + 20480 + off);
                bl[np * 2][0] = r4[0]; bl[np * 2][1] = r4[1];
                bl[np * 2 + 1][0] = r4[2]; bl[np * 2 + 1][1] = r4[3];
            }
#pragma unroll
            for (int mt = 0; mt < 2; mt++)
#pragma unroll
                for (int nt = 0; nt < 8; nt++) {
                    mma_h(acc[mt][nt], a[mt], bh[nt][0], bh[nt][1]);
                    mma_h(acc[mt][nt], a[mt], bl[nt][0], bl[nt][1]);
                }
        }
        __syncthreads();
    }

    // ---- epilogue: mask + energy out + stage E + fused softmax -> P ----
    float* E = (float*)sm;                 // [64][260]
    float* inv_s = (float*)(sm + 66560);   // [64]
#pragma unroll
    for (int mt = 0; mt < 2; mt++)
#pragma unroll
        for (int h = 0; h < 2; h++) {
            const int rl = wm * 32 + mt * 16 + (lane >> 2) + h * 8;
            const size_t grow = arow0 + rl;
#pragma unroll
            for (int nt = 0; nt < 8; nt++) {
                const int cl = wn * 64 + nt * 8 + (lane & 3) * 2;
                float v0 = acc[mt][nt][h * 2] +
                           (1.0f - (float)amask[b * TP + cl]) * (-1000.0f);
                float v1 = acc[mt][nt][h * 2 + 1] +
                           (1.0f - (float)amask[b * TP + cl + 1]) * (-1000.0f);
                *(float2*)&energy_out[grow * TP + cl] = make_float2(v0, v1);
                *(float2*)&E[rl * 260 + cl] = make_float2(v0, v1);
            }
        }
    __syncthreads();
    {
        const int r = t >> 2, q = t & 3;
        float* row = E + r * 260 + q * 64;
        float mx = -1e30f;
#pragma unroll 4
        for (int j = 0; j < 16; j++) {
            float4 v = *(const float4*)(row + j * 4);
            mx = fmaxf(mx, fmaxf(fmaxf(v.x, v.y), fmaxf(v.z, v.w)));
        }
        mx = fmaxf(mx, __shfl_xor_sync(0xffffffffu, mx, 1));
        mx = fmaxf(mx, __shfl_xor_sync(0xffffffffu, mx, 2));
        float ssum = 0.0f;
#pragma unroll 4
        for (int j = 0; j < 16; j++) {
            float4 v = *(float4*)(row + j * 4);
            v.x = fexp(v.x - mx); v.y = fexp(v.y - mx);
            v.z = fexp(v.z - mx); v.w = fexp(v.w - mx);
            ssum += v.x + v.y + v.z + v.w;
            *(float4*)(row + j * 4) = v;
        }
        ssum += __shfl_xor_sync(0xffffffffu, ssum, 1);
        ssum += __shfl_xor_sync(0xffffffffu, ssum, 2);
        if (q == 0) inv_s[r] = 1.0f / ssum;
    }
    __syncthreads();
    {
        const int r = t >> 2, q = t & 3;
        const float inv = inv_s[r];
        const float* row = E + r * 260 + q * 64;
        h16* pp = g_Ph + (arow0 + r) * TP + q * 64;
#pragma unroll 4
        for (int j = 0; j < 16; j++) {
            float4 v = *(const float4*)(row + j * 4);
            uint2 o;
            o.x = pack2h(__float2half_rn(v.x * inv), __float2half_rn(v.y * inv));
            o.y = pack2h(__float2half_rn(v.z * inv), __float2half_rn(v.w * inv));
            *(uint2*)(pp + j * 4) = o;
        }
    }
}

// ===== gemm2: 2-pass (a*bh + a*bl); att -> fp16 scratch ===================
#define G2_SMEM 49152
__global__ __launch_bounds__(256, 2)
void gemm2(const h16* __restrict__ Ah, int lda, int sA,
           const h16* __restrict__ Bh, const h16* __restrict__ Bl,
           int ldb, int sB, int K) {
    extern __shared__ char sm[];
    const uint32_t sbase = s2u(sm);
    const int t = threadIdx.x, lane = t & 31, wid = t >> 5;
    const int wm = wid >> 1, wn = wid & 1;
    const int b = blockIdx.z;
    const size_t arow0 = (size_t)b * sA + (size_t)blockIdx.y * 128;
    const size_t brow0 = (size_t)b * sB + (size_t)blockIdx.x * 128;
    const int NC = K / 32;

    float acc[2][8][4];
#pragma unroll
    for (int mt = 0; mt < 2; mt++)
#pragma unroll
        for (int nt = 0; nt < 8; nt++)
#pragma unroll
            for (int j = 0; j < 4; j++) acc[mt][nt][j] = 0.0f;

    ldth<128>(Ah, arow0, lda, 0, sbase, t);
    ldth<128>(Bh, brow0, ldb, 0, sbase + 8192, t);
    ldth<128>(Bl, brow0, ldb, 0, sbase + 16384, t);
    cp_commit();

    for (int c = 0; c < NC; c++) {
        if (c + 1 < NC) {
            uint32_t sn = sbase + ((c + 1) & 1) * 24576;
            const int k0 = (c + 1) * 32;
            ldth<128>(Ah, arow0, lda, k0, sn, t);
            ldth<128>(Bh, brow0, ldb, k0, sn + 8192, t);
            ldth<128>(Bl, brow0, ldb, k0, sn + 16384, t);
            cp_commit();
            cp_wait<1>();
        } else {
            cp_wait<0>();
        }
        __syncthreads();
        const uint32_t s = sbase + (c & 1) * 24576;
#pragma unroll
        for (int ks = 0; ks < 2; ks++) {
            uint32_t a[2][4], bh[8][2], bl[8][2];
#pragma unroll
            for (int mt = 0; mt < 2; mt++) {
                int row = wm * 32 + mt * 16 + (lane & 15);
                int q = ks * 2 + (lane >> 4);
                ldm4(a[mt], s + soff(row, q));
            }
            const int g = lane >> 3, w = lane & 7;
#pragma unroll
            for (int np = 0; np < 4; np++) {
                int ntl = np * 2 + (g >> 1);
                int row = wn * 64 + ntl * 8 + w;
                int q = ks * 2 + (g & 1);
                uint32_t off = soff(row, q);
                uint32_t r4[4];
                ldm4(r4, s + 8192 + off);
                bh[np * 2][0] = r4[0]; bh[np * 2][1] = r4[1];
                bh[np * 2 + 1][0] = r4[2]; bh[np * 2 + 1][1] = r4[3];
                ldm4(r4, s + 16384 + off);
                bl[np * 2][0] = r4[0]; bl[np * 2][1] = r4[1];
                bl[np * 2 + 1][0] = r4[2]; bl[np * 2 + 1][1] = r4[3];
            }
#pragma unroll
            for (int mt = 0; mt < 2; mt++)
#pragma unroll
                for (int nt = 0; nt < 8; nt++) {
                    mma_h(acc[mt][nt], a[mt], bh[nt][0], bh[nt][1]);
                    mma_h(acc[mt][nt], a[mt], bl[nt][0], bl[nt][1]);
                }
        }
        __syncthreads();
    }

#pragma unroll
    for (int mt = 0; mt < 2; mt++)
#pragma unroll
        for (int h = 0; h < 2; h++) {
            const int rl = wm * 32 + mt * 16 + (lane >> 2) + h * 8;
#pragma unroll
            for (int nt = 0; nt < 8; nt++) {
                const int cl = wn * 64 + nt * 8 + (lane & 3) * 2;
                const int mrow = blockIdx.y * 128 + rl;
                const int gcol = blockIdx.x * 128 + cl;
                *(uint32_t*)&g_att[((size_t)b * TF + mrow) * AD + gcol] =
                    pack2h(__float2half_rn(acc[mt][nt][h * 2]),
                           __float2half_rn(acc[mt][nt][h * 2 + 1]));
            }
        }
}

// ---------------- pointwise kernels ----------------
__global__ void cvt_kh(const float* __restrict__ in, h16* __restrict__ out,
                       size_t n4) {
    size_t i = (size_t)blockIdx.x * blockDim.x + threadIdx.x;
    if (i >= n4) return;
    float4 v = ((const float4*)in)[i];
    ((uint2*)out)[i] = make_uint2(
        pack2h(__float2half_rn(v.x), __float2half_rn(v.y)),
        pack2h(__float2half_rn(v.z), __float2half_rn(v.w)));
}
__global__ void split_kh(const float* __restrict__ in, h16* __restrict__ hi,
                         h16* __restrict__ lo, size_t n4) {
    size_t i = (size_t)blockIdx.x * blockDim.x + threadIdx.x;
    if (i >= n4) return;
    float4 v = ((const float4*)in)[i];
    h16 h0, h1, h2, h3, l0, l1, l2, l3;
    split1h(v.x, h0, l0); split1h(v.y, h1, l1);
    split1h(v.z, h2, l2); split1h(v.w, h3, l3);
    ((uint2*)hi)[i] = make_uint2(pack2h(h0, h1), pack2h(h2, h3));
    ((uint2*)lo)[i] = make_uint2(pack2h(l0, l1), pack2h(l2, l3));
}
__global__ void twt1_kh(const float* __restrict__ W, h16* __restrict__ hiT,
                        int K, int N) {
    __shared__ float tile[32][33];
    const int n0 = blockIdx.x * 32, k0 = blockIdx.y * 32;
    for (int r = threadIdx.y; r < 32; r += 8)
        tile[r][threadIdx.x] = W[(size_t)(k0 + r) * N + n0 + threadIdx.x];
    __syncthreads();
    for (int r = threadIdx.y; r < 32; r += 8)
        hiT[(size_t)(n0 + r) * K + k0 + threadIdx.x] =
            __float2half_rn(tile[threadIdx.x][r]);
}
__global__ void twt_kh(const float* __restrict__ W, h16* __restrict__ hiT,
                       h16* __restrict__ loT, int K, int N) {
    __shared__ float tile[32][33];
    const int n0 = blockIdx.x * 32, k0 = blockIdx.y * 32;
    for (int r = threadIdx.y; r < 32; r += 8)
        tile[r][threadIdx.x] = W[(size_t)(k0 + r) * N + n0 + threadIdx.x];
    __syncthreads();
    for (int r = threadIdx.y; r < 32; r += 8) {
        h16 h, l;
        split1h(tile[threadIdx.x][r], h, l);
        hiT[(size_t)(n0 + r) * K + k0 + threadIdx.x] = h;
        loT[(size_t)(n0 + r) * K + k0 + threadIdx.x] = l;
    }
}
__global__ __launch_bounds__(256)
void ln_k(const float* __restrict__ gamma, const float* __restrict__ beta,
          float* __restrict__ att_out) {
    const int lane = threadIdx.x & 31, wid = threadIdx.x >> 5;
    const size_t row = (size_t)blockIdx.x * 8 + wid;
    float avv[16], qv[16];
    {
        const uint2 a0 = *(const uint2*)(g_att + row * AD + lane * 16);
        const uint2 a1 = *(const uint2*)(g_att + row * AD + lane * 16 + 4);
        const uint2 a2 = *(const uint2*)(g_att + row * AD + lane * 16 + 8);
        const uint2 a3 = *(const uint2*)(g_att + row * AD + lane * 16 + 12);
        const uint32_t aw[8] = {a0.x, a0.y, a1.x, a1.y, a2.x, a2.y, a3.x, a3.y};
#pragma unroll
        for (int j = 0; j < 8; j++) {
            __half2 h = *(const __half2*)&aw[j];
            avv[2 * j]     = __half2float(h.x);
            avv[2 * j + 1] = __half2float(h.y);
        }
        const uint2 h0 = *(const uint2*)(g_qh + row * AD + lane * 16);
        const uint2 h1 = *(const uint2*)(g_qh + row * AD + lane * 16 + 4);
        const uint2 h2 = *(const uint2*)(g_qh + row * AD + lane * 16 + 8);
        const uint2 h3 = *(const uint2*)(g_qh + row * AD + lane * 16 + 12);
        const uint2 l0 = *(const uint2*)(g_ql + row * AD + lane * 16);
        const uint2 l1 = *(const uint2*)(g_ql + row * AD + lane * 16 + 4);
        const uint2 l2 = *(const uint2*)(g_ql + row * AD + lane * 16 + 8);
        const uint2 l3 = *(const uint2*)(g_ql + row * AD + lane * 16 + 12);
        const uint32_t hw[8] = {h0.x, h0.y, h1.x, h1.y, h2.x, h2.y, h3.x, h3.y};
        const uint32_t lw[8] = {l0.x, l0.y, l1.x, l1.y, l2.x, l2.y, l3.x, l3.y};
#pragma unroll
        for (int j = 0; j < 8; j++) {
            __half2 h = *(const __half2*)&hw[j];
            __half2 l = *(const __half2*)&lw[j];
            qv[2 * j]     = __half2float(h.x) + __half2float(l.x);
            qv[2 * j + 1] = __half2float(h.y) + __half2float(l.y);
        }
    }
    float s = 0.0f, ss = 0.0f;
#pragma unroll
    for (int j = 0; j < 16; j++) {
        s += avv[j] + qv[j];
        ss = fmaf(avv[j], avv[j], ss);
        ss = fmaf(qv[j], qv[j], ss);
    }
#pragma unroll
    for (int o = 16; o > 0; o >>= 1) {
        s  += __shfl_xor_sync(0xffffffffu, s, o);
        ss += __shfl_xor_sync(0xffffffffu, ss, o);
    }
    const float mu = s * (1.0f / 1024.0f);
    const float var = ss * (1.0f / 1024.0f) - mu * mu;
    const float rs = rsqrtf(var + 1e-5f);
    float* orow = att_out + row * 1024;
#pragma unroll
    for (int u = 0; u < 4; u++) {
        int c = lane * 16 + u * 4;
        float4 g = *(const float4*)(gamma + c);
        float4 be = *(const float4*)(beta + c);
        float4 o;
        o.x = (avv[u * 4]     - mu) * rs * g.x + be.x;
        o.y = (avv[u * 4 + 1] - mu) * rs * g.y + be.y;
        o.z = (avv[u * 4 + 2] - mu) * rs * g.z + be.z;
        o.w = (avv[u * 4 + 3] - mu) * rs * g.w + be.w;
        *(float4*)(orow + c) = o;
        int c2 = AD + c;
        g = *(const float4*)(gamma + c2);
        be = *(const float4*)(beta + c2);
        o.x = (qv[u * 4]     - mu) * rs * g.x + be.x;
        o.y = (qv[u * 4 + 1] - mu) * rs * g.y + be.y;
        o.z = (qv[u * 4 + 2] - mu) * rs * g.z + be.z;
        o.w = (qv[u * 4 + 3] - mu) * rs * g.w + be.w;
        *(float4*)(orow + c2) = o;
    }
}

// ---------------------------------------------------------------------------
extern "C" void kernel_launch(void* const* d_in, const int* in_sizes, int n_in,
                              void* d_out, int out_size) {
    const float* frame = (const float*)d_in[0];
    const float* phn   = (const float*)d_in[1];
    const int*   amask = (const int*)  d_in[2];
    const float* Wq    = (const float*)d_in[3];
    const float* bq    = (const float*)d_in[4];
    const float* Wk    = (const float*)d_in[5];
    const float* bk    = (const float*)d_in[6];
    const float* gamma = (const float*)d_in[7];
    const float* beta  = (const float*)d_in[8];

    float* out        = (float*)d_out;
    float* att_out    = out;
    float* energy_out = out + ((size_t)out_size - (size_t)BB * TF * TP);

    cudaFuncSetAttribute(gemm1, cudaFuncAttributeMaxDynamicSharedMemorySize, G1_SMEM);
    cudaFuncSetAttribute(gemm3, cudaFuncAttributeMaxDynamicSharedMemorySize, G3_SMEM);
    cudaFuncSetAttribute(energy_sm, cudaFuncAttributeMaxDynamicSharedMemorySize, GE_SMEM);
    cudaFuncSetAttribute(gemm2, cudaFuncAttributeMaxDynamicSharedMemorySize, G2_SMEM);

    h16 *fh, *ph_, *pl_, *wqh, *wkh, *wkl;
    h16 *qh, *kh, *kl, *kth, *ktl, *Ph;
    cudaGetSymbolAddress((void**)&fh, g_fh);
    cudaGetSymbolAddress((void**)&ph_, g_ph);
    cudaGetSymbolAddress((void**)&pl_, g_pl);
    cudaGetSymbolAddress((void**)&wqh, g_wqh);
    cudaGetSymbolAddress((void**)&wkh, g_wkh);
    cudaGetSymbolAddress((void**)&wkl, g_wkl);
    cudaGetSymbolAddress((void**)&qh, g_qh);
    cudaGetSymbolAddress((void**)&kh, g_kh);
    cudaGetSymbolAddress((void**)&kl, g_kl);
    cudaGetSymbolAddress((void**)&kth, g_kth);
    cudaGetSymbolAddress((void**)&ktl, g_ktl);
    cudaGetSymbolAddress((void**)&Ph, g_Ph);

    {
        size_t n4 = (size_t)BB * TF * FD / 4;
        cvt_kh<<<(unsigned)(n4 / 256), 256>>>(frame, fh, n4);
    }
    {
        size_t n4 = (size_t)BB * TP * PD / 4;
        split_kh<<<(unsigned)(n4 / 256), 256>>>(phn, ph_, pl_, n4);
    }
    twt1_kh<<<dim3(AD / 32, FD / 32), dim3(32, 8)>>>(Wq, wqh, FD, AD);
    twt_kh<<<dim3(AD / 32, PD / 32), dim3(32, 8)>>>(Wk, wkh, wkl, PD, AD);

    // projections: K 3-pass (accurate), Q 1-pass
    gemm3<<<dim3(4, 64), 256, G3_SMEM>>>(ph_, pl_, PD, wkh, wkl, PD, PD, bk);
    gemm1<<<dim3(4, 512), 256, G1_SMEM>>>(fh, FD, wqh, FD, FD, bq);

    // energy + mask + fused softmax -> energy_out + P
    energy_sm<<<dim3(1, TF / 64, BB), 256, GE_SMEM>>>(qh, kh, kl, amask,
                                                      energy_out);
    // att = P @ k (2-pass) -> fp16 scratch
    gemm2<<<dim3(4, 16, BB), 256, G2_SMEM>>>(Ph, TP, TF, kth, ktl, TP, AD, TP);
    // LayerNorm
    ln_k<<<BB * TF / 8, 256>>>(gamma, beta, att_out);
}

// round 16
// speedup vs baseline: 1.0692x; 1.0692x over previous
#include <cuda_runtime.h>
#include <cuda_fp16.h>
#include <math.h>
#include <stdint.h>

#define BB 32
#define TF 2048
#define TP 256
#define FD 768
#define PD 512
#define AD 512
typedef __half h16;

// ---------------- device scratch ----------------
__device__ h16 g_fh[(size_t)BB * TF * FD];                       // frame fp16
__device__ h16 g_ph[(size_t)BB * TP * PD], g_pl[(size_t)BB * TP * PD];
__device__ h16 g_wqh[AD * FD];                                   // Wq^T fp16
__device__ h16 g_wkh[AD * PD], g_wkl[AD * PD];
__device__ h16 g_qh[(size_t)BB * TF * AD], g_ql[(size_t)BB * TF * AD];
__device__ h16 g_kh[(size_t)BB * TP * AD], g_kl[(size_t)BB * TP * AD];
__device__ h16 g_kth[(size_t)BB * AD * TP], g_ktl[(size_t)BB * AD * TP];
__device__ h16 g_Ph[(size_t)BB * TF * TP];
__device__ h16 g_att[(size_t)BB * TF * AD];   // fp16 scratch (pre-LN att)

// ---------------- helpers ----------------
__device__ __forceinline__ uint32_t s2u(const void* p) {
    uint32_t a;
    asm("{ .reg .u64 t; cvta.to.shared.u64 t, %1; cvt.u32.u64 %0, t; }"
        : "=r"(a) : "l"(p));
    return a;
}
__device__ __forceinline__ void split1h(float v, h16& h, h16& l) {
    h = __float2half_rn(v);
    l = __float2half_rn(v - __half2float(h));
}
__device__ __forceinline__ uint32_t pack2h(h16 a, h16 b) {
    __half2 v; v.x = a; v.y = b;
    return *(uint32_t*)&v;
}
__device__ __forceinline__ void cp16(uint32_t dst, const void* src) {
    asm volatile("cp.async.cg.shared.global [%0], [%1], 16;" :: "r"(dst), "l"(src));
}
__device__ __forceinline__ void cp_commit() { asm volatile("cp.async.commit_group;"); }
template <int N>
__device__ __forceinline__ void cp_wait() {
    asm volatile("cp.async.wait_group %0;" :: "n"(N));
}
__device__ __forceinline__ void ldm4(uint32_t* r, uint32_t addr) {
    asm volatile("ldmatrix.sync.aligned.m8n8.x4.shared.b16 {%0,%1,%2,%3}, [%4];"
                 : "=r"(r[0]), "=r"(r[1]), "=r"(r[2]), "=r"(r[3]) : "r"(addr));
}
__device__ __forceinline__ void mma_h(float* c, const uint32_t* a,
                                      uint32_t b0, uint32_t b1) {
    asm volatile("mma.sync.aligned.m16n8k16.row.col.f32.f16.f16.f32 "
                 "{%0,%1,%2,%3}, {%4,%5,%6,%7}, {%8,%9}, {%0,%1,%2,%3};"
                 : "+f"(c[0]), "+f"(c[1]), "+f"(c[2]), "+f"(c[3])
                 : "r"(a[0]), "r"(a[1]), "r"(a[2]), "r"(a[3]), "r"(b0), "r"(b1));
}
__device__ __forceinline__ float fexp(float x) {
    float y = fmaxf(x * 1.44269504f, -125.0f);
    float i = rintf(y);
    float f = y - i;
    float p = 1.3333558146e-3f;
    p = fmaf(p, f, 9.6181291076e-3f);
    p = fmaf(p, f, 5.5504108664e-2f);
    p = fmaf(p, f, 2.4022650696e-1f);
    p = fmaf(p, f, 6.9314718056e-1f);
    p = fmaf(p, f, 1.0f);
    float s = __int_as_float(((int)i + 127) << 23);
    return p * s;
}
// 64B-row swizzle: row*64 bytes, 16B unit q in 0..3, XOR with (row>>1)&3
__device__ __forceinline__ uint32_t soff(int row, int q) {
    return (uint32_t)(row * 64 + ((q ^ ((row >> 1) & 3)) << 4));
}
// cp.async [128 x 32] fp16 K-major tile into swizzled smem (256 threads)
__device__ __forceinline__ void ldth(const h16* __restrict__ src, size_t row0,
                                     int ld, int k0, uint32_t dst, int t) {
#pragma unroll
    for (int it = 0; it < 2; it++) {
        int u = it * 256 + t;
        int row = u >> 2, q = u & 3;
        cp16(dst + soff(row, q), src + (row0 + row) * (size_t)ld + k0 + q * 8);
    }
}

// ===== gemm1: 1-pass fp16 C[128,128] (projQ); 3-stage pipeline ============
#define G1_SMEM (3 * 16384)
__global__ __launch_bounds__(256, 2)
void gemm1(const h16* __restrict__ Ah, int lda, const h16* __restrict__ Bh,
           int ldb, int K, const float* __restrict__ bias) {
    extern __shared__ char sm[];
    const uint32_t sbase = s2u(sm);
    const int t = threadIdx.x, lane = t & 31, wid = t >> 5;
    const int wm = wid >> 1, wn = wid & 1;
    const size_t arow0 = (size_t)blockIdx.y * 128;
    const size_t brow0 = (size_t)blockIdx.x * 128;
    const int NC = K / 32;

    float acc[2][8][4];
#pragma unroll
    for (int mt = 0; mt < 2; mt++)
#pragma unroll
        for (int nt = 0; nt < 8; nt++)
#pragma unroll
            for (int j = 0; j < 4; j++) acc[mt][nt][j] = 0.0f;

#define G1_ISSUE(cc)                                                     \
    do {                                                                 \
        uint32_t sn = sbase + ((cc) % 3) * 16384;                        \
        ldth(Ah, arow0, lda, (cc) * 32, sn, t);                          \
        ldth(Bh, brow0, ldb, (cc) * 32, sn + 8192, t);                   \
        cp_commit();                                                     \
    } while (0)

    G1_ISSUE(0);
    G1_ISSUE(1);

    for (int c = 0; c < NC; c++) {
        if (c + 2 < NC) { G1_ISSUE(c + 2); cp_wait<2>(); }
        else if (c + 1 < NC) cp_wait<1>();
        else cp_wait<0>();
        __syncthreads();
        const uint32_t s = sbase + (c % 3) * 16384;
#pragma unroll
        for (int ks = 0; ks < 2; ks++) {
            uint32_t a[2][4], bb[8][2];
#pragma unroll
            for (int mt = 0; mt < 2; mt++) {
                int row = wm * 32 + mt * 16 + (lane & 15);
                int q = ks * 2 + (lane >> 4);
                ldm4(a[mt], s + soff(row, q));
            }
            const int g = lane >> 3, w = lane & 7;
#pragma unroll
            for (int np = 0; np < 4; np++) {
                int ntl = np * 2 + (g >> 1);
                int row = wn * 64 + ntl * 8 + w;
                int q = ks * 2 + (g & 1);
                uint32_t r4[4];
                ldm4(r4, s + 8192 + soff(row, q));
                bb[np * 2][0] = r4[0]; bb[np * 2][1] = r4[1];
                bb[np * 2 + 1][0] = r4[2]; bb[np * 2 + 1][1] = r4[3];
            }
#pragma unroll
            for (int mt = 0; mt < 2; mt++)
#pragma unroll
                for (int nt = 0; nt < 8; nt++)
                    mma_h(acc[mt][nt], a[mt], bb[nt][0], bb[nt][1]);
        }
        __syncthreads();
    }
#undef G1_ISSUE
#pragma unroll
    for (int mt = 0; mt < 2; mt++)
#pragma unroll
        for (int h = 0; h < 2; h++) {
            const int rl = wm * 32 + mt * 16 + (lane >> 2) + h * 8;
            const size_t gr = (size_t)blockIdx.y * 128 + rl;
#pragma unroll
            for (int nt = 0; nt < 8; nt++) {
                const int cl = wn * 64 + nt * 8 + (lane & 3) * 2;
                const int gc = blockIdx.x * 128 + cl;
                float v0 = acc[mt][nt][h * 2] + bias[gc];
                float v1 = acc[mt][nt][h * 2 + 1] + bias[gc + 1];
                h16 h0, l0, h1, l1;
                split1h(v0, h0, l0);
                split1h(v1, h1, l1);
                *(uint32_t*)&g_qh[gr * AD + gc] = pack2h(h0, h1);
                *(uint32_t*)&g_ql[gr * AD + gc] = pack2h(l0, l1);
            }
        }
}

// ===== gemm3: 3-pass fp16 split (projK); 3-stage pipeline =================
#define G3_SMEM (3 * 32768)
__global__ __launch_bounds__(256, 2)
void gemm3(const h16* __restrict__ Ah, const h16* __restrict__ Al, int lda,
           const h16* __restrict__ Bh, const h16* __restrict__ Bl,
           int ldb, int K, const float* __restrict__ bias) {
    extern __shared__ char sm[];
    const uint32_t sbase = s2u(sm);
    const int t = threadIdx.x, lane = t & 31, wid = t >> 5;
    const int wm = wid >> 1, wn = wid & 1;
    const size_t arow0 = (size_t)blockIdx.y * 128;
    const size_t brow0 = (size_t)blockIdx.x * 128;
    const int NC = K / 32;

    float acc[2][8][4];
#pragma unroll
    for (int mt = 0; mt < 2; mt++)
#pragma unroll
        for (int nt = 0; nt < 8; nt++)
#pragma unroll
            for (int j = 0; j < 4; j++) acc[mt][nt][j] = 0.0f;

#define G3_ISSUE(cc)                                                     \
    do {                                                                 \
        uint32_t sn = sbase + ((cc) % 3) * 32768;                        \
        const int k0 = (cc) * 32;                                        \
        ldth(Ah, arow0, lda, k0, sn, t);                                 \
        ldth(Al, arow0, lda, k0, sn + 8192, t);                          \
        ldth(Bh, brow0, ldb, k0, sn + 16384, t);                         \
        ldth(Bl, brow0, ldb, k0, sn + 24576, t);                         \
        cp_commit();                                                     \
    } while (0)

    G3_ISSUE(0);
    G3_ISSUE(1);

    for (int c = 0; c < NC; c++) {
        if (c + 2 < NC) { G3_ISSUE(c + 2); cp_wait<2>(); }
        else if (c + 1 < NC) cp_wait<1>();
        else cp_wait<0>();
        __syncthreads();
        const uint32_t s = sbase + (c % 3) * 32768;
#pragma unroll
        for (int ks = 0; ks < 2; ks++) {
            uint32_t ah[2][4], al[2][4], bh[8][2], bl[8][2];
#pragma unroll
            for (int mt = 0; mt < 2; mt++) {
                int row = wm * 32 + mt * 16 + (lane & 15);
                int q = ks * 2 + (lane >> 4);
                uint32_t off = soff(row, q);
                ldm4(ah[mt], s + off);
                ldm4(al[mt], s + 8192 + off);
            }
            const int g = lane >> 3, w = lane & 7;
#pragma unroll
            for (int np = 0; np < 4; np++) {
                int ntl = np * 2 + (g >> 1);
                int row = wn * 64 + ntl * 8 + w;
                int q = ks * 2 + (g & 1);
                uint32_t off = soff(row, q);
                uint32_t r4[4];
                ldm4(r4, s + 16384 + off);
                bh[np * 2][0] = r4[0]; bh[np * 2][1] = r4[1];
                bh[np * 2 + 1][0] = r4[2]; bh[np * 2 + 1][1] = r4[3];
                ldm4(r4, s + 24576 + off);
                bl[np * 2][0] = r4[0]; bl[np * 2][1] = r4[1];
                bl[np * 2 + 1][0] = r4[2]; bl[np * 2 + 1][1] = r4[3];
            }
#pragma unroll
            for (int mt = 0; mt < 2; mt++)
#pragma unroll
                for (int nt = 0; nt < 8; nt++) {
                    mma_h(acc[mt][nt], ah[mt], bh[nt][0], bh[nt][1]);
                    mma_h(acc[mt][nt], ah[mt], bl[nt][0], bl[nt][1]);
                    mma_h(acc[mt][nt], al[mt], bh[nt][0], bh[nt][1]);
                }
        }
        __syncthreads();
    }
#undef G3_ISSUE

#pragma unroll
    for (int mt = 0; mt < 2; mt++)
#pragma unroll
        for (int h = 0; h < 2; h++) {
            const int rl = wm * 32 + mt * 16 + (lane >> 2) + h * 8;
            const size_t gr = (size_t)blockIdx.y * 128 + rl;
#pragma unroll
            for (int nt = 0; nt < 8; nt++) {
                const int cl = wn * 64 + nt * 8 + (lane & 3) * 2;
                const int gc = blockIdx.x * 128 + cl;
                float v0 = acc[mt][nt][h * 2] + bias[gc];
                float v1 = acc[mt][nt][h * 2 + 1] + bias[gc + 1];
                h16 h0, l0, h1, l1;
                split1h(v0, h0, l0);
                split1h(v1, h1, l1);
                *(uint32_t*)&g_kh[gr * AD + gc] = pack2h(h0, h1);
                *(uint32_t*)&g_kl[gr * AD + gc] = pack2h(l0, l1);
                const int bb = (int)(gr >> 8), p = (int)(gr & 255);
                g_kth[((size_t)bb * AD + gc) * TP + p] = h0;
                g_ktl[((size_t)bb * AD + gc) * TP + p] = l0;
                g_kth[((size_t)bb * AD + gc + 1) * TP + p] = h1;
                g_ktl[((size_t)bb * AD + gc + 1) * TP + p] = l1;
            }
        }
}

// ===== gemm2: 2-pass; MODE 2 energy(+mask), 3 att(fp16); 3-stage ==========
#define G2_SMEM (3 * 24576)
template <int MODE>
__global__ __launch_bounds__(256, 2)
void gemm2(const h16* __restrict__ Ah, int lda, int sA,
           const h16* __restrict__ Bh, const h16* __restrict__ Bl,
           int ldb, int sB, int K, const void* __restrict__ aux,
           float* __restrict__ outp) {
    extern __shared__ char sm[];
    const uint32_t sbase = s2u(sm);
    const int t = threadIdx.x, lane = t & 31, wid = t >> 5;
    const int wm = wid >> 1, wn = wid & 1;
    const int b = blockIdx.z;
    const size_t arow0 = (size_t)b * sA + (size_t)blockIdx.y * 128;
    const size_t brow0 = (size_t)b * sB + (size_t)blockIdx.x * 128;
    const int NC = K / 32;

    float acc[2][8][4];
#pragma unroll
    for (int mt = 0; mt < 2; mt++)
#pragma unroll
        for (int nt = 0; nt < 8; nt++)
#pragma unroll
            for (int j = 0; j < 4; j++) acc[mt][nt][j] = 0.0f;

#define G2_ISSUE(cc)                                                     \
    do {                                                                 \
        uint32_t sn = sbase + ((cc) % 3) * 24576;                        \
        const int k0 = (cc) * 32;                                        \
        ldth(Ah, arow0, lda, k0, sn, t);                                 \
        ldth(Bh, brow0, ldb, k0, sn + 8192, t);                          \
        ldth(Bl, brow0, ldb, k0, sn + 16384, t);                         \
        cp_commit();                                                     \
    } while (0)

    G2_ISSUE(0);
    G2_ISSUE(1);

    for (int c = 0; c < NC; c++) {
        if (c + 2 < NC) { G2_ISSUE(c + 2); cp_wait<2>(); }
        else if (c + 1 < NC) cp_wait<1>();
        else cp_wait<0>();
        __syncthreads();
        const uint32_t s = sbase + (c % 3) * 24576;
#pragma unroll
        for (int ks = 0; ks < 2; ks++) {
            uint32_t a[2][4], bh[8][2], bl[8][2];
#pragma unroll
            for (int mt = 0; mt < 2; mt++) {
                int row = wm * 32 + mt * 16 + (lane & 15);
                int q = ks * 2 + (lane >> 4);
                ldm4(a[mt], s + soff(row, q));
            }
            const int g = lane >> 3, w = lane & 7;
#pragma unroll
            for (int np = 0; np < 4; np++) {
                int ntl = np * 2 + (g >> 1);
                int row = wn * 64 + ntl * 8 + w;
                int q = ks * 2 + (g & 1);
                uint32_t off = soff(row, q);
                uint32_t r4[4];
                ldm4(r4, s + 8192 + off);
                bh[np * 2][0] = r4[0]; bh[np * 2][1] = r4[1];
                bh[np * 2 + 1][0] = r4[2]; bh[np * 2 + 1][1] = r4[3];
                ldm4(r4, s + 16384 + off);
                bl[np * 2][0] = r4[0]; bl[np * 2][1] = r4[1];
                bl[np * 2 + 1][0] = r4[2]; bl[np * 2 + 1][1] = r4[3];
            }
#pragma unroll
            for (int mt = 0; mt < 2; mt++)
#pragma unroll
                for (int nt = 0; nt < 8; nt++) {
                    mma_h(acc[mt][nt], a[mt], bh[nt][0], bh[nt][1]);
                    mma_h(acc[mt][nt], a[mt], bl[nt][0], bl[nt][1]);
                }
        }
        __syncthreads();
    }
#undef G2_ISSUE

#pragma unroll
    for (int mt = 0; mt < 2; mt++)
#pragma unroll
        for (int h = 0; h < 2; h++) {
            const int rl = wm * 32 + mt * 16 + (lane >> 2) + h * 8;
#pragma unroll
            for (int nt = 0; nt < 8; nt++) {
                const int cl = wn * 64 + nt * 8 + (lane & 3) * 2;
                float v0 = acc[mt][nt][h * 2];
                float v1 = acc[mt][nt][h * 2 + 1];
                const int mrow = blockIdx.y * 128 + rl;
                const int gcol = blockIdx.x * 128 + cl;
                if (MODE == 2) {
                    const int* am = (const int*)aux;
                    v0 += (1.0f - (float)am[b * TP + gcol]) * (-1000.0f);
                    v1 += (1.0f - (float)am[b * TP + gcol + 1]) * (-1000.0f);
                    *(float2*)&outp[((size_t)b * TF + mrow) * TP + gcol] =
                        make_float2(v0, v1);
                } else {
                    *(uint32_t*)&g_att[((size_t)b * TF + mrow) * AD + gcol] =
                        pack2h(__float2half_rn(v0), __float2half_rn(v1));
                }
            }
        }
}

// ---------------- pointwise kernels ----------------
__global__ void cvt_kh(const float* __restrict__ in, h16* __restrict__ out,
                       size_t n4) {
    size_t i = (size_t)blockIdx.x * blockDim.x + threadIdx.x;
    if (i >= n4) return;
    float4 v = ((const float4*)in)[i];
    ((uint2*)out)[i] = make_uint2(
        pack2h(__float2half_rn(v.x), __float2half_rn(v.y)),
        pack2h(__float2half_rn(v.z), __float2half_rn(v.w)));
}
__global__ void split_kh(const float* __restrict__ in, h16* __restrict__ hi,
                         h16* __restrict__ lo, size_t n4) {
    size_t i = (size_t)blockIdx.x * blockDim.x + threadIdx.x;
    if (i >= n4) return;
    float4 v = ((const float4*)in)[i];
    h16 h0, h1, h2, h3, l0, l1, l2, l3;
    split1h(v.x, h0, l0); split1h(v.y, h1, l1);
    split1h(v.z, h2, l2); split1h(v.w, h3, l3);
    ((uint2*)hi)[i] = make_uint2(pack2h(h0, h1), pack2h(h2, h3));
    ((uint2*)lo)[i] = make_uint2(pack2h(l0, l1), pack2h(l2, l3));
}
__global__ void twt1_kh(const float* __restrict__ W, h16* __restrict__ hiT,
                        int K, int N) {
    __shared__ float tile[32][33];
    const int n0 = blockIdx.x * 32, k0 = blockIdx.y * 32;
    for (int r = threadIdx.y; r < 32; r += 8)
        tile[r][threadIdx.x] = W[(size_t)(k0 + r) * N + n0 + threadIdx.x];
    __syncthreads();
    for (int r = threadIdx.y; r < 32; r += 8)
        hiT[(size_t)(n0 + r) * K + k0 + threadIdx.x] =
            __float2half_rn(tile[threadIdx.x][r]);
}
__global__ void twt_kh(const float* __restrict__ W, h16* __restrict__ hiT,
                       h16* __restrict__ loT, int K, int N) {
    __shared__ float tile[32][33];
    const int n0 = blockIdx.x * 32, k0 = blockIdx.y * 32;
    for (int r = threadIdx.y; r < 32; r += 8)
        tile[r][threadIdx.x] = W[(size_t)(k0 + r) * N + n0 + threadIdx.x];
    __syncthreads();
    for (int r = threadIdx.y; r < 32; r += 8) {
        h16 h, l;
        split1h(tile[threadIdx.x][r], h, l);
        hiT[(size_t)(n0 + r) * K + k0 + threadIdx.x] = h;
        loT[(size_t)(n0 + r) * K + k0 + threadIdx.x] = l;
    }
}
__global__ __launch_bounds__(256)
void softmax_k(const float* __restrict__ energy) {
    const int lane = threadIdx.x & 31, wid = threadIdx.x >> 5;
    const size_t row = (size_t)blockIdx.x * 8 + wid;
    const float* e = energy + row * TP + lane * 8;
    float v[8];
    *(float4*)&v[0] = *(const float4*)(e);
    *(float4*)&v[4] = *(const float4*)(e + 4);
    float mx = v[0];
#pragma unroll
    for (int j = 1; j < 8; j++) mx = fmaxf(mx, v[j]);
#pragma unroll
    for (int o = 16; o > 0; o >>= 1)
        mx = fmaxf(mx, __shfl_xor_sync(0xffffffffu, mx, o));
    float s = 0.0f;
#pragma unroll
    for (int j = 0; j < 8; j++) { v[j] = fexp(v[j] - mx); s += v[j]; }
#pragma unroll
    for (int o = 16; o > 0; o >>= 1)
        s += __shfl_xor_sync(0xffffffffu, s, o);
    const float inv = 1.0f / s;
    h16* ph = g_Ph + row * TP + lane * 8;
#pragma unroll
    for (int j = 0; j < 8; j += 2) {
        *(uint32_t*)(ph + j) = pack2h(__float2half_rn(v[j] * inv),
                                      __float2half_rn(v[j + 1] * inv));
    }
}
__global__ __launch_bounds__(256)
void ln_k(const float* __restrict__ gamma, const float* __restrict__ beta,
          float* __restrict__ att_out) {
    const int lane = threadIdx.x & 31, wid = threadIdx.x >> 5;
    const size_t row = (size_t)blockIdx.x * 8 + wid;
    float avv[16], qv[16];
    {
        const uint2 a0 = *(const uint2*)(g_att + row * AD + lane * 16);
        const uint2 a1 = *(const uint2*)(g_att + row * AD + lane * 16 + 4);
        const uint2 a2 = *(const uint2*)(g_att + row * AD + lane * 16 + 8);
        const uint2 a3 = *(const uint2*)(g_att + row * AD + lane * 16 + 12);
        const uint32_t aw[8] = {a0.x, a0.y, a1.x, a1.y, a2.x, a2.y, a3.x, a3.y};
#pragma unroll
        for (int j = 0; j < 8; j++) {
            __half2 h = *(const __half2*)&aw[j];
            avv[2 * j]     = __half2float(h.x);
            avv[2 * j + 1] = __half2float(h.y);
        }
        const uint2 h0 = *(const uint2*)(g_qh + row * AD + lane * 16);
        const uint2 h1 = *(const uint2*)(g_qh + row * AD + lane * 16 + 4);
        const uint2 h2 = *(const uint2*)(g_qh + row * AD + lane * 16 + 8);
        const uint2 h3 = *(const uint2*)(g_qh + row * AD + lane * 16 + 12);
        const uint2 l0 = *(const uint2*)(g_ql + row * AD + lane * 16);
        const uint2 l1 = *(const uint2*)(g_ql + row * AD + lane * 16 + 4);
        const uint2 l2 = *(const uint2*)(g_ql + row * AD + lane * 16 + 8);
        const uint2 l3 = *(const uint2*)(g_ql + row * AD + lane * 16 + 12);
        const uint32_t hw[8] = {h0.x, h0.y, h1.x, h1.y, h2.x, h2.y, h3.x, h3.y};
        const uint32_t lw[8] = {l0.x, l0.y, l1.x, l1.y, l2.x, l2.y, l3.x, l3.y};
#pragma unroll
        for (int j = 0; j < 8; j++) {
            __half2 h = *(const __half2*)&hw[j];
            __half2 l = *(const __half2*)&lw[j];
            qv[2 * j]     = __half2float(h.x) + __half2float(l.x);
            qv[2 * j + 1] = __half2float(h.y) + __half2float(l.y);
        }
    }
    float s = 0.0f, ss = 0.0f;
#pragma unroll
    for (int j = 0; j < 16; j++) {
        s += avv[j] + qv[j];
        ss = fmaf(avv[j], avv[j], ss);
        ss = fmaf(qv[j], qv[j], ss);
    }
#pragma unroll
    for (int o = 16; o > 0; o >>= 1) {
        s  += __shfl_xor_sync(0xffffffffu, s, o);
        ss += __shfl_xor_sync(0xffffffffu, ss, o);
    }
    const float mu = s * (1.0f / 1024.0f);
    const float var = ss * (1.0f / 1024.0f) - mu * mu;
    const float rs = rsqrtf(var + 1e-5f);
    float* orow = att_out + row * 1024;
#pragma unroll
    for (int u = 0; u < 4; u++) {
        int c = lane * 16 + u * 4;
        float4 g = *(const float4*)(gamma + c);
        float4 be = *(const float4*)(beta + c);
        float4 o;
        o.x = (avv[u * 4]     - mu) * rs * g.x + be.x;
        o.y = (avv[u * 4 + 1] - mu) * rs * g.y + be.y;
        o.z = (avv[u * 4 + 2] - mu) * rs * g.z + be.z;
        o.w = (avv[u * 4 + 3] - mu) * rs * g.w + be.w;
        *(float4*)(orow + c) = o;
        int c2 = AD + c;
        g = *(const float4*)(gamma + c2);
        be = *(const float4*)(beta + c2);
        o.x = (qv[u * 4]     - mu) * rs * g.x + be.x;
        o.y = (qv[u * 4 + 1] - mu) * rs * g.y + be.y;
        o.z = (qv[u * 4 + 2] - mu) * rs * g.z + be.z;
        o.w = (qv[u * 4 + 3] - mu) * rs * g.w + be.w;
        *(float4*)(orow + c2) = o;
    }
}

// ---------------------------------------------------------------------------
extern "C" void kernel_launch(void* const* d_in, const int* in_sizes, int n_in,
                              void* d_out, int out_size) {
    const float* frame = (const float*)d_in[0];
    const float* phn   = (const float*)d_in[1];
    const int*   amask = (const int*)  d_in[2];
    const float* Wq    = (const float*)d_in[3];
    const float* bq    = (const float*)d_in[4];
    const float* Wk    = (const float*)d_in[5];
    const float* bk    = (const float*)d_in[6];
    const float* gamma = (const float*)d_in[7];
    const float* beta  = (const float*)d_in[8];

    float* out        = (float*)d_out;
    float* att_out    = out;
    float* energy_out = out + ((size_t)out_size - (size_t)BB * TF * TP);

    cudaFuncSetAttribute(gemm1, cudaFuncAttributeMaxDynamicSharedMemorySize, G1_SMEM);
    cudaFuncSetAttribute(gemm3, cudaFuncAttributeMaxDynamicSharedMemorySize, G3_SMEM);
    cudaFuncSetAttribute(gemm2<2>, cudaFuncAttributeMaxDynamicSharedMemorySize, G2_SMEM);
    cudaFuncSetAttribute(gemm2<3>, cudaFuncAttributeMaxDynamicSharedMemorySize, G2_SMEM);

    h16 *fh, *ph_, *pl_, *wqh, *wkh, *wkl;
    h16 *qh, *kh, *kl, *kth, *ktl, *Ph;
    cudaGetSymbolAddress((void**)&fh, g_fh);
    cudaGetSymbolAddress((void**)&ph_, g_ph);
    cudaGetSymbolAddress((void**)&pl_, g_pl);
    cudaGetSymbolAddress((void**)&wqh, g_wqh);
    cudaGetSymbolAddress((void**)&wkh, g_wkh);
    cudaGetSymbolAddress((void**)&wkl, g_wkl);
    cudaGetSymbolAddress((void**)&qh, g_qh);
    cudaGetSymbolAddress((void**)&kh, g_kh);
    cudaGetSymbolAddress((void**)&kl, g_kl);
    cudaGetSymbolAddress((void**)&kth, g_kth);
    cudaGetSymbolAddress((void**)&ktl, g_ktl);
    cudaGetSymbolAddress((void**)&Ph, g_Ph);

    {
        size_t n4 = (size_t)BB * TF * FD / 4;
        cvt_kh<<<(unsigned)(n4 / 256), 256>>>(frame, fh, n4);
    }
    {
        size_t n4 = (size_t)BB * TP * PD / 4;
        split_kh<<<(unsigned)(n4 / 256), 256>>>(phn, ph_, pl_, n4);
    }
    twt1_kh<<<dim3(AD / 32, FD / 32), dim3(32, 8)>>>(Wq, wqh, FD, AD);
    twt_kh<<<dim3(AD / 32, PD / 32), dim3(32, 8)>>>(Wk, wkh, wkl, PD, AD);

    // projections: K 3-pass (accurate), Q 1-pass
    gemm3<<<dim3(4, 64), 256, G3_SMEM>>>(ph_, pl_, PD, wkh, wkl, PD, PD, bk);
    gemm1<<<dim3(4, 512), 256, G1_SMEM>>>(fh, FD, wqh, FD, FD, bq);

    // energy = q @ k^T + mask (2-pass)
    gemm2<2><<<dim3(2, 16, BB), 256, G2_SMEM>>>(qh, AD, TF, kh, kl, AD, TP,
                                                AD, amask, energy_out);
    // softmax -> P (fp16)
    softmax_k<<<BB * TF / 8, 256>>>(energy_out);
    // att = P @ k (2-pass) -> fp16 scratch
    gemm2<3><<<dim3(4, 16, BB), 256, G2_SMEM>>>(Ph, TP, TF, kth, ktl, TP, AD,
                                                TP, nullptr, nullptr);
    // LayerNorm
    ln_k<<<BB * TF / 8, 256>>>(gamma, beta, att_out);
}

// round 17
// speedup vs baseline: 1.1898x; 1.1128x over previous
#include <cuda_runtime.h>
#include <cuda_fp16.h>
#include <math.h>
#include <stdint.h>

#define BB 32
#define TF 2048
#define TP 256
#define FD 768
#define PD 512
#define AD 512
typedef __half h16;

// ---------------- device scratch ----------------
__device__ h16 g_fh[(size_t)BB * TF * FD];                       // frame fp16
__device__ h16 g_ph[(size_t)BB * TP * PD], g_pl[(size_t)BB * TP * PD];
__device__ h16 g_wqh[AD * FD];                                   // Wq^T fp16
__device__ h16 g_wkh[AD * PD], g_wkl[AD * PD];
__device__ h16 g_qh[(size_t)BB * TF * AD];                       // q fp16
__device__ h16 g_kh[(size_t)BB * TP * AD];                       // k fp16
__device__ h16 g_kth[(size_t)BB * AD * TP], g_ktl[(size_t)BB * AD * TP];
__device__ h16 g_Ph[(size_t)BB * TF * TP];
__device__ h16 g_att[(size_t)BB * TF * AD];   // fp16 scratch (pre-LN att)

// ---------------- helpers ----------------
__device__ __forceinline__ uint32_t s2u(const void* p) {
    uint32_t a;
    asm("{ .reg .u64 t; cvta.to.shared.u64 t, %1; cvt.u32.u64 %0, t; }"
        : "=r"(a) : "l"(p));
    return a;
}
__device__ __forceinline__ void split1h(float v, h16& h, h16& l) {
    h = __float2half_rn(v);
    l = __float2half_rn(v - __half2float(h));
}
__device__ __forceinline__ uint32_t pack2h(h16 a, h16 b) {
    __half2 v; v.x = a; v.y = b;
    return *(uint32_t*)&v;
}
__device__ __forceinline__ void cp16(uint32_t dst, const void* src) {
    asm volatile("cp.async.cg.shared.global [%0], [%1], 16;" :: "r"(dst), "l"(src));
}
__device__ __forceinline__ void cp_commit() { asm volatile("cp.async.commit_group;"); }
template <int N>
__device__ __forceinline__ void cp_wait() {
    asm volatile("cp.async.wait_group %0;" :: "n"(N));
}
__device__ __forceinline__ void ldm4(uint32_t* r, uint32_t addr) {
    asm volatile("ldmatrix.sync.aligned.m8n8.x4.shared.b16 {%0,%1,%2,%3}, [%4];"
                 : "=r"(r[0]), "=r"(r[1]), "=r"(r[2]), "=r"(r[3]) : "r"(addr));
}
__device__ __forceinline__ void mma_h(float* c, const uint32_t* a,
                                      uint32_t b0, uint32_t b1) {
    asm volatile("mma.sync.aligned.m16n8k16.row.col.f32.f16.f16.f32 "
                 "{%0,%1,%2,%3}, {%4,%5,%6,%7}, {%8,%9}, {%0,%1,%2,%3};"
                 : "+f"(c[0]), "+f"(c[1]), "+f"(c[2]), "+f"(c[3])
                 : "r"(a[0]), "r"(a[1]), "r"(a[2]), "r"(a[3]), "r"(b0), "r"(b1));
}
__device__ __forceinline__ float fexp(float x) {
    float y = fmaxf(x * 1.44269504f, -125.0f);
    float i = rintf(y);
    float f = y - i;
    float p = 1.3333558146e-3f;
    p = fmaf(p, f, 9.6181291076e-3f);
    p = fmaf(p, f, 5.5504108664e-2f);
    p = fmaf(p, f, 2.4022650696e-1f);
    p = fmaf(p, f, 6.9314718056e-1f);
    p = fmaf(p, f, 1.0f);
    float s = __int_as_float(((int)i + 127) << 23);
    return p * s;
}
// 64B-row swizzle
__device__ __forceinline__ uint32_t soff(int row, int q) {
    return (uint32_t)(row * 64 + ((q ^ ((row >> 1) & 3)) << 4));
}
// cp.async [128 x 32] fp16 K-major tile into swizzled smem (256 threads)
__device__ __forceinline__ void ldth(const h16* __restrict__ src, size_t row0,
                                     int ld, int k0, uint32_t dst, int t) {
#pragma unroll
    for (int it = 0; it < 2; it++) {
        int u = it * 256 + t;
        int row = u >> 2, q = u & 3;
        cp16(dst + soff(row, q), src + (row0 + row) * (size_t)ld + k0 + q * 8);
    }
}

// ===== gemm1: 1-pass fp16 C[128,128]; MODE 0 projQ, MODE 2 energy =========
#define G1_SMEM (3 * 16384)
template <int MODE>
__global__ __launch_bounds__(256, 2)
void gemm1(const h16* __restrict__ Ah, int lda, int sA,
           const h16* __restrict__ Bh, int ldb, int sB, int K,
           const void* __restrict__ aux, float* __restrict__ outp) {
    extern __shared__ char sm[];
    const uint32_t sbase = s2u(sm);
    const int t = threadIdx.x, lane = t & 31, wid = t >> 5;
    const int wm = wid >> 1, wn = wid & 1;
    const int b = blockIdx.z;
    const size_t arow0 = (size_t)b * sA + (size_t)blockIdx.y * 128;
    const size_t brow0 = (size_t)b * sB + (size_t)blockIdx.x * 128;
    const int NC = K / 32;

    float acc[2][8][4];
#pragma unroll
    for (int mt = 0; mt < 2; mt++)
#pragma unroll
        for (int nt = 0; nt < 8; nt++)
#pragma unroll
            for (int j = 0; j < 4; j++) acc[mt][nt][j] = 0.0f;

#define G1_ISSUE(cc)                                                     \
    do {                                                                 \
        uint32_t sn = sbase + ((cc) % 3) * 16384;                        \
        ldth(Ah, arow0, lda, (cc) * 32, sn, t);                          \
        ldth(Bh, brow0, ldb, (cc) * 32, sn + 8192, t);                   \
        cp_commit();                                                     \
    } while (0)

    G1_ISSUE(0);
    G1_ISSUE(1);

    for (int c = 0; c < NC; c++) {
        if (c + 2 < NC) { G1_ISSUE(c + 2); cp_wait<2>(); }
        else if (c + 1 < NC) cp_wait<1>();
        else cp_wait<0>();
        __syncthreads();
        const uint32_t s = sbase + (c % 3) * 16384;
#pragma unroll
        for (int ks = 0; ks < 2; ks++) {
            uint32_t a[2][4], bb[8][2];
#pragma unroll
            for (int mt = 0; mt < 2; mt++) {
                int row = wm * 32 + mt * 16 + (lane & 15);
                int q = ks * 2 + (lane >> 4);
                ldm4(a[mt], s + soff(row, q));
            }
            const int g = lane >> 3, w = lane & 7;
#pragma unroll
            for (int np = 0; np < 4; np++) {
                int ntl = np * 2 + (g >> 1);
                int row = wn * 64 + ntl * 8 + w;
                int q = ks * 2 + (g & 1);
                uint32_t r4[4];
                ldm4(r4, s + 8192 + soff(row, q));
                bb[np * 2][0] = r4[0]; bb[np * 2][1] = r4[1];
                bb[np * 2 + 1][0] = r4[2]; bb[np * 2 + 1][1] = r4[3];
            }
#pragma unroll
            for (int mt = 0; mt < 2; mt++)
#pragma unroll
                for (int nt = 0; nt < 8; nt++)
                    mma_h(acc[mt][nt], a[mt], bb[nt][0], bb[nt][1]);
        }
        __syncthreads();
    }
#undef G1_ISSUE
#pragma unroll
    for (int mt = 0; mt < 2; mt++)
#pragma unroll
        for (int h = 0; h < 2; h++) {
            const int rl = wm * 32 + mt * 16 + (lane >> 2) + h * 8;
#pragma unroll
            for (int nt = 0; nt < 8; nt++) {
                const int cl = wn * 64 + nt * 8 + (lane & 3) * 2;
                float v0 = acc[mt][nt][h * 2];
                float v1 = acc[mt][nt][h * 2 + 1];
                if (MODE == 0) {
                    const float* bias = (const float*)aux;
                    const size_t gr = (size_t)blockIdx.y * 128 + rl;
                    const int gc = blockIdx.x * 128 + cl;
                    v0 += bias[gc];
                    v1 += bias[gc + 1];
                    *(uint32_t*)&g_qh[gr * AD + gc] =
                        pack2h(__float2half_rn(v0), __float2half_rn(v1));
                } else {
                    const int* am = (const int*)aux;
                    const int mrow = blockIdx.y * 128 + rl;
                    const int gcol = blockIdx.x * 128 + cl;
                    v0 += (1.0f - (float)am[b * TP + gcol]) * (-1000.0f);
                    v1 += (1.0f - (float)am[b * TP + gcol + 1]) * (-1000.0f);
                    *(float2*)&outp[((size_t)b * TF + mrow) * TP + gcol] =
                        make_float2(v0, v1);
                }
            }
        }
}

// ===== gemm3: 3-pass fp16 split (projK); 3-stage pipeline =================
#define G3_SMEM (3 * 32768)
__global__ __launch_bounds__(256, 2)
void gemm3(const h16* __restrict__ Ah, const h16* __restrict__ Al, int lda,
           const h16* __restrict__ Bh, const h16* __restrict__ Bl,
           int ldb, int K, const float* __restrict__ bias) {
    extern __shared__ char sm[];
    const uint32_t sbase = s2u(sm);
    const int t = threadIdx.x, lane = t & 31, wid = t >> 5;
    const int wm = wid >> 1, wn = wid & 1;
    const size_t arow0 = (size_t)blockIdx.y * 128;
    const size_t brow0 = (size_t)blockIdx.x * 128;
    const int NC = K / 32;

    float acc[2][8][4];
#pragma unroll
    for (int mt = 0; mt < 2; mt++)
#pragma unroll
        for (int nt = 0; nt < 8; nt++)
#pragma unroll
            for (int j = 0; j < 4; j++) acc[mt][nt][j] = 0.0f;

#define G3_ISSUE(cc)                                                     \
    do {                                                                 \
        uint32_t sn = sbase + ((cc) % 3) * 32768;                        \
        const int k0 = (cc) * 32;                                        \
        ldth(Ah, arow0, lda, k0, sn, t);                                 \
        ldth(Al, arow0, lda, k0, sn + 8192, t);                          \
        ldth(Bh, brow0, ldb, k0, sn + 16384, t);                         \
        ldth(Bl, brow0, ldb, k0, sn + 24576, t);                         \
        cp_commit();                                                     \
    } while (0)

    G3_ISSUE(0);
    G3_ISSUE(1);

    for (int c = 0; c < NC; c++) {
        if (c + 2 < NC) { G3_ISSUE(c + 2); cp_wait<2>(); }
        else if (c + 1 < NC) cp_wait<1>();
        else cp_wait<0>();
        __syncthreads();
        const uint32_t s = sbase + (c % 3) * 32768;
#pragma unroll
        for (int ks = 0; ks < 2; ks++) {
            uint32_t ah[2][4], al[2][4], bh[8][2], bl[8][2];
#pragma unroll
            for (int mt = 0; mt < 2; mt++) {
                int row = wm * 32 + mt * 16 + (lane & 15);
                int q = ks * 2 + (lane >> 4);
                uint32_t off = soff(row, q);
                ldm4(ah[mt], s + off);
                ldm4(al[mt], s + 8192 + off);
            }
            const int g = lane >> 3, w = lane & 7;
#pragma unroll
            for (int np = 0; np < 4; np++) {
                int ntl = np * 2 + (g >> 1);
                int row = wn * 64 + ntl * 8 + w;
                int q = ks * 2 + (g & 1);
                uint32_t off = soff(row, q);
                uint32_t r4[4];
                ldm4(r4, s + 16384 + off);
                bh[np * 2][0] = r4[0]; bh[np * 2][1] = r4[1];
                bh[np * 2 + 1][0] = r4[2]; bh[np * 2 + 1][1] = r4[3];
                ldm4(r4, s + 24576 + off);
                bl[np * 2][0] = r4[0]; bl[np * 2][1] = r4[1];
                bl[np * 2 + 1][0] = r4[2]; bl[np * 2 + 1][1] = r4[3];
            }
#pragma unroll
            for (int mt = 0; mt < 2; mt++)
#pragma unroll
                for (int nt = 0; nt < 8; nt++) {
                    mma_h(acc[mt][nt], ah[mt], bh[nt][0], bh[nt][1]);
                    mma_h(acc[mt][nt], ah[mt], bl[nt][0], bl[nt][1]);
                    mma_h(acc[mt][nt], al[mt], bh[nt][0], bh[nt][1]);
                }
        }
        __syncthreads();
    }
#undef G3_ISSUE

#pragma unroll
    for (int mt = 0; mt < 2; mt++)
#pragma unroll
        for (int h = 0; h < 2; h++) {
            const int rl = wm * 32 + mt * 16 + (lane >> 2) + h * 8;
            const size_t gr = (size_t)blockIdx.y * 128 + rl;
#pragma unroll
            for (int nt = 0; nt < 8; nt++) {
                const int cl = wn * 64 + nt * 8 + (lane & 3) * 2;
                const int gc = blockIdx.x * 128 + cl;
                float v0 = acc[mt][nt][h * 2] + bias[gc];
                float v1 = acc[mt][nt][h * 2 + 1] + bias[gc + 1];
                h16 h0, l0, h1, l1;
                split1h(v0, h0, l0);
                split1h(v1, h1, l1);
                *(uint32_t*)&g_kh[gr * AD + gc] = pack2h(h0, h1);
                const int bb = (int)(gr >> 8), p = (int)(gr & 255);
                g_kth[((size_t)bb * AD + gc) * TP + p] = h0;
                g_ktl[((size_t)bb * AD + gc) * TP + p] = l0;
                g_kth[((size_t)bb * AD + gc + 1) * TP + p] = h1;
                g_ktl[((size_t)bb * AD + gc + 1) * TP + p] = l1;
            }
        }
}

// ===== gemm2: 2-pass (a*bh + a*bl); att -> fp16 scratch; 3-stage ==========
#define G2_SMEM (3 * 24576)
__global__ __launch_bounds__(256, 2)
void gemm2(const h16* __restrict__ Ah, int lda, int sA,
           const h16* __restrict__ Bh, const h16* __restrict__ Bl,
           int ldb, int sB, int K) {
    extern __shared__ char sm[];
    const uint32_t sbase = s2u(sm);
    const int t = threadIdx.x, lane = t & 31, wid = t >> 5;
    const int wm = wid >> 1, wn = wid & 1;
    const int b = blockIdx.z;
    const size_t arow0 = (size_t)b * sA + (size_t)blockIdx.y * 128;
    const size_t brow0 = (size_t)b * sB + (size_t)blockIdx.x * 128;
    const int NC = K / 32;

    float acc[2][8][4];
#pragma unroll
    for (int mt = 0; mt < 2; mt++)
#pragma unroll
        for (int nt = 0; nt < 8; nt++)
#pragma unroll
            for (int j = 0; j < 4; j++) acc[mt][nt][j] = 0.0f;

#define G2_ISSUE(cc)                                                     \
    do {                                                                 \
        uint32_t sn = sbase + ((cc) % 3) * 24576;                        \
        const int k0 = (cc) * 32;                                        \
        ldth(Ah, arow0, lda, k0, sn, t);                                 \
        ldth(Bh, brow0, ldb, k0, sn + 8192, t);                          \
        ldth(Bl, brow0, ldb, k0, sn + 16384, t);                         \
        cp_commit();                                                     \
    } while (0)

    G2_ISSUE(0);
    G2_ISSUE(1);

    for (int c = 0; c < NC; c++) {
        if (c + 2 < NC) { G2_ISSUE(c + 2); cp_wait<2>(); }
        else if (c + 1 < NC) cp_wait<1>();
        else cp_wait<0>();
        __syncthreads();
        const uint32_t s = sbase + (c % 3) * 24576;
#pragma unroll
        for (int ks = 0; ks < 2; ks++) {
            uint32_t a[2][4], bh[8][2], bl[8][2];
#pragma unroll
            for (int mt = 0; mt < 2; mt++) {
                int row = wm * 32 + mt * 16 + (lane & 15);
                int q = ks * 2 + (lane >> 4);
                ldm4(a[mt], s + soff(row, q));
            }
            const int g = lane >> 3, w = lane & 7;
#pragma unroll
            for (int np = 0; np < 4; np++) {
                int ntl = np * 2 + (g >> 1);
                int row = wn * 64 + ntl * 8 + w;
                int q = ks * 2 + (g & 1);
                uint32_t off = soff(row, q);
                uint32_t r4[4];
                ldm4(r4, s + 8192 + off);
                bh[np * 2][0] = r4[0]; bh[np * 2][1] = r4[1];
                bh[np * 2 + 1][0] = r4[2]; bh[np * 2 + 1][1] = r4[3];
                ldm4(r4, s + 16384 + off);
                bl[np * 2][0] = r4[0]; bl[np * 2][1] = r4[1];
                bl[np * 2 + 1][0] = r4[2]; bl[np * 2 + 1][1] = r4[3];
            }
#pragma unroll
            for (int mt = 0; mt < 2; mt++)
#pragma unroll
                for (int nt = 0; nt < 8; nt++) {
                    mma_h(acc[mt][nt], a[mt], bh[nt][0], bh[nt][1]);
                    mma_h(acc[mt][nt], a[mt], bl[nt][0], bl[nt][1]);
                }
        }
        __syncthreads();
    }
#undef G2_ISSUE

#pragma unroll
    for (int mt = 0; mt < 2; mt++)
#pragma unroll
        for (int h = 0; h < 2; h++) {
            const int rl = wm * 32 + mt * 16 + (lane >> 2) + h * 8;
#pragma unroll
            for (int nt = 0; nt < 8; nt++) {
                const int cl = wn * 64 + nt * 8 + (lane & 3) * 2;
                const int mrow = blockIdx.y * 128 + rl;
                const int gcol = blockIdx.x * 128 + cl;
                *(uint32_t*)&g_att[((size_t)b * TF + mrow) * AD + gcol] =
                    pack2h(__float2half_rn(acc[mt][nt][h * 2]),
                           __float2half_rn(acc[mt][nt][h * 2 + 1]));
            }
        }
}

// ---------------- pointwise kernels ----------------
__global__ void cvt_kh(const float* __restrict__ in, h16* __restrict__ out,
                       size_t n4) {
    size_t i = (size_t)blockIdx.x * blockDim.x + threadIdx.x;
    if (i >= n4) return;
    float4 v = ((const float4*)in)[i];
    ((uint2*)out)[i] = make_uint2(
        pack2h(__float2half_rn(v.x), __float2half_rn(v.y)),
        pack2h(__float2half_rn(v.z), __float2half_rn(v.w)));
}
__global__ void split_kh(const float* __restrict__ in, h16* __restrict__ hi,
                         h16* __restrict__ lo, size_t n4) {
    size_t i = (size_t)blockIdx.x * blockDim.x + threadIdx.x;
    if (i >= n4) return;
    float4 v = ((const float4*)in)[i];
    h16 h0, h1, h2, h3, l0, l1, l2, l3;
    split1h(v.x, h0, l0); split1h(v.y, h1, l1);
    split1h(v.z, h2, l2); split1h(v.w, h3, l3);
    ((uint2*)hi)[i] = make_uint2(pack2h(h0, h1), pack2h(h2, h3));
    ((uint2*)lo)[i] = make_uint2(pack2h(l0, l1), pack2h(l2, l3));
}
__global__ void twt1_kh(const float* __restrict__ W, h16* __restrict__ hiT,
                        int K, int N) {
    __shared__ float tile[32][33];
    const int n0 = blockIdx.x * 32, k0 = blockIdx.y * 32;
    for (int r = threadIdx.y; r < 32; r += 8)
        tile[r][threadIdx.x] = W[(size_t)(k0 + r) * N + n0 + threadIdx.x];
    __syncthreads();
    for (int r = threadIdx.y; r < 32; r += 8)
        hiT[(size_t)(n0 + r) * K + k0 + threadIdx.x] =
            __float2half_rn(tile[threadIdx.x][r]);
}
__global__ void twt_kh(const float* __restrict__ W, h16* __restrict__ hiT,
                       h16* __restrict__ loT, int K, int N) {
    __shared__ float tile[32][33];
    const int n0 = blockIdx.x * 32, k0 = blockIdx.y * 32;
    for (int r = threadIdx.y; r < 32; r += 8)
        tile[r][threadIdx.x] = W[(size_t)(k0 + r) * N + n0 + threadIdx.x];
    __syncthreads();
    for (int r = threadIdx.y; r < 32; r += 8) {
        h16 h, l;
        split1h(tile[threadIdx.x][r], h, l);
        hiT[(size_t)(n0 + r) * K + k0 + threadIdx.x] = h;
        loT[(size_t)(n0 + r) * K + k0 + threadIdx.x] = l;
    }
}
__global__ __launch_bounds__(256)
void softmax_k(const float* __restrict__ energy) {
    const int lane = threadIdx.x & 31, wid = threadIdx.x >> 5;
    const size_t row = (size_t)blockIdx.x * 8 + wid;
    const float* e = energy + row * TP + lane * 8;
    float v[8];
    *(float4*)&v[0] = *(const float4*)(e);
    *(float4*)&v[4] = *(const float4*)(e + 4);
    float mx = v[0];
#pragma unroll
    for (int j = 1; j < 8; j++) mx = fmaxf(mx, v[j]);
#pragma unroll
    for (int o = 16; o > 0; o >>= 1)
        mx = fmaxf(mx, __shfl_xor_sync(0xffffffffu, mx, o));
    float s = 0.0f;
#pragma unroll
    for (int j = 0; j < 8; j++) { v[j] = fexp(v[j] - mx); s += v[j]; }
#pragma unroll
    for (int o = 16; o > 0; o >>= 1)
        s += __shfl_xor_sync(0xffffffffu, s, o);
    const float inv = 1.0f / s;
    h16* ph = g_Ph + row * TP + lane * 8;
#pragma unroll
    for (int j = 0; j < 8; j += 2) {
        *(uint32_t*)(ph + j) = pack2h(__float2half_rn(v[j] * inv),
                                      __float2half_rn(v[j + 1] * inv));
    }
}
__global__ __launch_bounds__(256)
void ln_k(const float* __restrict__ gamma, const float* __restrict__ beta,
          float* __restrict__ att_out) {
    const int lane = threadIdx.x & 31, wid = threadIdx.x >> 5;
    const size_t row = (size_t)blockIdx.x * 8 + wid;
    float avv[16], qv[16];
    {
        const uint2 a0 = *(const uint2*)(g_att + row * AD + lane * 16);
        const uint2 a1 = *(const uint2*)(g_att + row * AD + lane * 16 + 4);
        const uint2 a2 = *(const uint2*)(g_att + row * AD + lane * 16 + 8);
        const uint2 a3 = *(const uint2*)(g_att + row * AD + lane * 16 + 12);
        const uint32_t aw[8] = {a0.x, a0.y, a1.x, a1.y, a2.x, a2.y, a3.x, a3.y};
#pragma unroll
        for (int j = 0; j < 8; j++) {
            __half2 h = *(const __half2*)&aw[j];
            avv[2 * j]     = __half2float(h.x);
            avv[2 * j + 1] = __half2float(h.y);
        }
        const uint2 h0 = *(const uint2*)(g_qh + row * AD + lane * 16);
        const uint2 h1 = *(const uint2*)(g_qh + row * AD + lane * 16 + 4);
        const uint2 h2 = *(const uint2*)(g_qh + row * AD + lane * 16 + 8);
        const uint2 h3 = *(const uint2*)(g_qh + row * AD + lane * 16 + 12);
        const uint32_t hw[8] = {h0.x, h0.y, h1.x, h1.y, h2.x, h2.y, h3.x, h3.y};
#pragma unroll
        for (int j = 0; j < 8; j++) {
            __half2 h = *(const __half2*)&hw[j];
            qv[2 * j]     = __half2float(h.x);
            qv[2 * j + 1] = __half2float(h.y);
        }
    }
    float s = 0.0f, ss = 0.0f;
#pragma unroll
    for (int j = 0; j < 16; j++) {
        s += avv[j] + qv[j];
        ss = fmaf(avv[j], avv[j], ss);
        ss = fmaf(qv[j], qv[j], ss);
    }
#pragma unroll
    for (int o = 16; o > 0; o >>= 1) {
        s  += __shfl_xor_sync(0xffffffffu, s, o);
        ss += __shfl_xor_sync(0xffffffffu, ss, o);
    }
    const float mu = s * (1.0f / 1024.0f);
    const float var = ss * (1.0f / 1024.0f) - mu * mu;
    const float rs = rsqrtf(var + 1e-5f);
    float* orow = att_out + row * 1024;
#pragma unroll
    for (int u = 0; u < 4; u++) {
        int c = lane * 16 + u * 4;
        float4 g = *(const float4*)(gamma + c);
        float4 be = *(const float4*)(beta + c);
        float4 o;
        o.x = (avv[u * 4]     - mu) * rs * g.x + be.x;
        o.y = (avv[u * 4 + 1] - mu) * rs * g.y + be.y;
        o.z = (avv[u * 4 + 2] - mu) * rs * g.z + be.z;
        o.w = (avv[u * 4 + 3] - mu) * rs * g.w + be.w;
        *(float4*)(orow + c) = o;
        int c2 = AD + c;
        g = *(const float4*)(gamma + c2);
        be = *(const float4*)(beta + c2);
        o.x = (qv[u * 4]     - mu) * rs * g.x + be.x;
        o.y = (qv[u * 4 + 1] - mu) * rs * g.y + be.y;
        o.z = (qv[u * 4 + 2] - mu) * rs * g.z + be.z;
        o.w = (qv[u * 4 + 3] - mu) * rs * g.w + be.w;
        *(float4*)(orow + c2) = o;
    }
}

// ---------------------------------------------------------------------------
extern "C" void kernel_launch(void* const* d_in, const int* in_sizes, int n_in,
                              void* d_out, int out_size) {
    const float* frame = (const float*)d_in[0];
    const float* phn   = (const float*)d_in[1];
    const int*   amask = (const int*)  d_in[2];
    const float* Wq    = (const float*)d_in[3];
    const float* bq    = (const float*)d_in[4];
    const float* Wk    = (const float*)d_in[5];
    const float* bk    = (const float*)d_in[6];
    const float* gamma = (const float*)d_in[7];
    const float* beta  = (const float*)d_in[8];

    float* out        = (float*)d_out;
    float* att_out    = out;
    float* energy_out = out + ((size_t)out_size - (size_t)BB * TF * TP);

    cudaFuncSetAttribute(gemm1<0>, cudaFuncAttributeMaxDynamicSharedMemorySize, G1_SMEM);
    cudaFuncSetAttribute(gemm1<2>, cudaFuncAttributeMaxDynamicSharedMemorySize, G1_SMEM);
    cudaFuncSetAttribute(gemm3, cudaFuncAttributeMaxDynamicSharedMemorySize, G3_SMEM);
    cudaFuncSetAttribute(gemm2, cudaFuncAttributeMaxDynamicSharedMemorySize, G2_SMEM);

    h16 *fh, *ph_, *pl_, *wqh, *wkh, *wkl;
    h16 *qh, *kh, *kth, *ktl, *Ph;
    cudaGetSymbolAddress((void**)&fh, g_fh);
    cudaGetSymbolAddress((void**)&ph_, g_ph);
    cudaGetSymbolAddress((void**)&pl_, g_pl);
    cudaGetSymbolAddress((void**)&wqh, g_wqh);
    cudaGetSymbolAddress((void**)&wkh, g_wkh);
    cudaGetSymbolAddress((void**)&wkl, g_wkl);
    cudaGetSymbolAddress((void**)&qh, g_qh);
    cudaGetSymbolAddress((void**)&kh, g_kh);
    cudaGetSymbolAddress((void**)&kth, g_kth);
    cudaGetSymbolAddress((void**)&ktl, g_ktl);
    cudaGetSymbolAddress((void**)&Ph, g_Ph);

    {
        size_t n4 = (size_t)BB * TF * FD / 4;
        cvt_kh<<<(unsigned)(n4 / 256), 256>>>(frame, fh, n4);
    }
    {
        size_t n4 = (size_t)BB * TP * PD / 4;
        split_kh<<<(unsigned)(n4 / 256), 256>>>(phn, ph_, pl_, n4);
    }
    twt1_kh<<<dim3(AD / 32, FD / 32), dim3(32, 8)>>>(Wq, wqh, FD, AD);
    twt_kh<<<dim3(AD / 32, PD / 32), dim3(32, 8)>>>(Wk, wkh, wkl, PD, AD);

    // projections: K 3-pass (accurate), Q 1-pass
    gemm3<<<dim3(4, 64), 256, G3_SMEM>>>(ph_, pl_, PD, wkh, wkl, PD, PD, bk);
    gemm1<0><<<dim3(4, 512, 1), 256, G1_SMEM>>>(fh, FD, 0, wqh, FD, 0, FD,
                                                bq, nullptr);

    // energy = q @ k^T + mask (1-pass: qh*kh)
    gemm1<2><<<dim3(2, 16, BB), 256, G1_SMEM>>>(qh, AD, TF, kh, AD, TP, AD,
                                                amask, energy_out);
    // softmax -> P (fp16)
    softmax_k<<<BB * TF / 8, 256>>>(energy_out);
    // att = P @ k (2-pass) -> fp16 scratch
    gemm2<<<dim3(4, 16, BB), 256, G2_SMEM>>>(Ph, TP, TF, kth, ktl, TP, AD, TP);
    // LayerNorm (q from qh only)
    ln_k<<<BB * TF / 8, 256>>>(gamma, beta, att_out);
}